// round 13
// baseline (speedup 1.0000x reference)
#include <cuda_runtime.h>
#include <cuda_fp16.h>
#include <cstdint>

#define DINL __device__ __forceinline__

namespace {
constexpr int Bn = 32768;
constexpr int Tn = 187;
constexpr int Hn = 256;
constexpr int BM = 224;          // batch rows per CTA -> 147 CTAs = ONE wave on 148 SMs
constexpr int NT = 448;          // 14 warps x 16 rows

constexpr int WH_STRIDE = 528;   // bytes per Wh row (264 f16) -> conflict-free ldsm
constexpr int W1_STRIDE = 144;   // bytes per W1 row (72 f16)
constexpr int ST_STRIDE = 144;   // per-thread stash stride (36 u32; 32 used) -> 9 chunks, odd
                                 // multiplier mod 32 -> conflict-free STS/LDS.128

constexpr int OFF_WH    = 0;                          // 256*528 = 135168
constexpr int OFF_STASH = OFF_WH + Hn * WH_STRIDE;    // 135168, 448*144 = 64512 (W1 later)
constexpr int OFF_WXB   = OFF_STASH + NT * ST_STRIDE; // 199680, float2{Wx,b} x256
constexpr int OFF_B1    = OFF_WXB + Hn * 8;           // 201728
constexpr int OFF_W2    = OFF_B1 + 64 * 4;            // 201984
constexpr int OFF_B2    = OFF_W2 + 320 * 4;           // 203264
constexpr int SMEM_TOTAL = OFF_B2 + 32;               // 203296
static_assert(SMEM_TOTAL <= 232448, "smem overflow");
static_assert(Hn * W1_STRIDE <= NT * ST_STRIDE, "W1 must fit in stash");
}

// ---------------- helpers ----------------
DINL uint32_t smem_u32(const void* p) {
    uint32_t a;
    asm("{ .reg .u64 t; cvta.to.shared.u64 t, %1; cvt.u32.u64 %0, t; }" : "=r"(a) : "l"(p));
    return a;
}
DINL void ldsm4t(uint32_t& r0, uint32_t& r1, uint32_t& r2, uint32_t& r3, uint32_t addr) {
    asm volatile("ldmatrix.sync.aligned.m8n8.x4.trans.shared.b16 {%0,%1,%2,%3}, [%4];"
                 : "=r"(r0), "=r"(r1), "=r"(r2), "=r"(r3) : "r"(addr));
}
DINL void mma16816(float* d, uint32_t a0, uint32_t a1, uint32_t a2, uint32_t a3,
                   uint32_t b0, uint32_t b1) {
    asm volatile("mma.sync.aligned.m16n8k16.row.col.f32.f16.f16.f32 "
                 "{%0,%1,%2,%3}, {%4,%5,%6,%7}, {%8,%9}, {%0,%1,%2,%3};"
                 : "+f"(d[0]), "+f"(d[1]), "+f"(d[2]), "+f"(d[3])
                 : "r"(a0), "r"(a1), "r"(a2), "r"(a3), "r"(b0), "r"(b1));
}
DINL uint32_t pack_f16x2(float lo, float hi) {
    uint32_t r;
    asm("cvt.rn.f16x2.f32 %0, %1, %2;" : "=r"(r) : "f"(hi), "f"(lo));
    return r;
}
DINL uint32_t tanh2(uint32_t v) {
    uint32_t r;
    asm("tanh.approx.f16x2 %0, %1;" : "=r"(r) : "r"(v));
    return r;
}

// ---------------- kernel ----------------
__global__ void __launch_bounds__(NT, 1)
rnn_kernel(const float* __restrict__ gx,  const float* __restrict__ gWx,
           const float* __restrict__ gWh, const float* __restrict__ gbr,
           const float* __restrict__ gW1, const float* __restrict__ gb1,
           const float* __restrict__ gW2, const float* __restrict__ gb2,
           float* __restrict__ gout) {
    extern __shared__ char smem[];
    const int tid  = threadIdx.x;
    const int lane = tid & 31;
    const int wid  = tid >> 5;
    const int m0   = blockIdx.x * BM;
    const int gid  = lane >> 2;      // row group 0..7
    const int tig  = lane & 3;       // thread-in-group

    // ---- cooperative staging (Wh + consts; x streams from L2 via LDG) ----
    for (int i = tid; i < Hn * Hn; i += NT) {            // Wh[k][n] -> k-major padded f16
        int k = i >> 8, n = i & 255;
        *(__half*)(smem + OFF_WH + k * WH_STRIDE + n * 2) = __float2half(gWh[i]);
    }
    for (int i = tid; i < Hn; i += NT)
        ((float2*)(smem + OFF_WXB))[i] = make_float2(gWx[i], gbr[i]);
    for (int i = tid; i < 64; i += NT)  ((float*)(smem + OFF_B1))[i] = gb1[i];
    for (int i = tid; i < 320; i += NT) ((float*)(smem + OFF_W2))[i] = gW2[i];
    if (tid < 5) ((float*)(smem + OFF_B2))[tid] = gb2[tid];
    __syncthreads();

    // ---- per-warp setup ----
    const uint32_t sb = smem_u32(smem);
    const int tq = lane >> 3;   // ldmatrix x4 slot
    const uint32_t lds_wh = sb + OFF_WH + ((tq & 1) * 8 + (lane & 7)) * WH_STRIDE + (tq >> 1) * 16;
    char* stash = smem + OFF_STASH + tid * ST_STRIDE;    // thread-private carry stash
    const float4* wxb4 = (const float4*)(smem + OFF_WXB);   // {w0,b0,w1,b1} per even col pair

    const int row0 = m0 + wid * 16 + gid;                // this thread's 2 batch rows
    const size_t roff0 = (size_t)(row0     < Bn ? row0     : Bn - 1) * Tn;  // clamped for LDG
    const size_t roff8 = (size_t)(row0 + 8 < Bn ? row0 + 8 : Bn - 1) * Tn;

    uint32_t hA[64];   // h as A fragments: hA[2t2]=(row gid, cols 8t2+2tig,+1), hA[2t2+1]=(+8)

    // ---- t = 0: h0 = tanh(x0*Wx + b) ----
    {
        float xg = gx[roff0], xg8 = gx[roff8];
        #pragma unroll
        for (int t2 = 0; t2 < 32; ++t2) {
            float4 wb = wxb4[4 * t2 + tig];
            hA[2 * t2]     = tanh2(pack_f16x2(fmaf(xg,  wb.x, wb.y), fmaf(xg,  wb.z, wb.w)));
            hA[2 * t2 + 1] = tanh2(pack_f16x2(fmaf(xg8, wb.x, wb.y), fmaf(xg8, wb.z, wb.w)));
        }
    }
    float xn0 = gx[roff0 + 1], xn8 = gx[roff8 + 1];

    // ---- recurrence: t = 1..186 (warp-private, no sync) ----
    #pragma unroll 1
    for (int t = 1; t < Tn; ++t) {
        const float xg = xn0, xg8 = xn8;
        const int tnext = (t + 1 < Tn) ? t + 1 : t;      // prefetch next step's x (L2-resident)
        xn0 = gx[roff0 + tnext];
        xn8 = gx[roff8 + tnext];

        uint32_t held[32];                               // reg carry for groups 4..7
        #pragma unroll
        for (int g = 0; g < 8; ++g) {                    // 32-col n-group: n8-tiles 4g..4g+3
            float d[4][4];
            #pragma unroll
            for (int j = 0; j < 4; ++j) {                // D init = x_t*Wx + b
                float4 wb = wxb4[16 * g + 4 * j + tig];
                d[j][0] = fmaf(xg,  wb.x, wb.y);
                d[j][1] = fmaf(xg,  wb.z, wb.w);
                d[j][2] = fmaf(xg8, wb.x, wb.y);
                d[j][3] = fmaf(xg8, wb.z, wb.w);
            }
            #pragma unroll
            for (int kc = 0; kc < 16; ++kc) {
                const uint32_t a0 = hA[4 * kc], a1 = hA[4 * kc + 1];
                const uint32_t a2 = hA[4 * kc + 2], a3 = hA[4 * kc + 3];
                const uint32_t base = lds_wh + kc * 16 * WH_STRIDE + g * 64;
                #pragma unroll
                for (int q = 0; q < 2; ++q) {            // 2 n8-tiles per ldsm.x4
                    uint32_t b0, b1, b2, b3;
                    ldsm4t(b0, b1, b2, b3, base + q * 32);
                    mma16816(d[2 * q],     a0, a1, a2, a3, b0, b1);
                    mma16816(d[2 * q + 1], a0, a1, a2, a3, b2, b3);
                }
            }
            // pack -> tanh: group g yields hA slots 8g..8g+7 for next step
            uint32_t L[8];
            #pragma unroll
            for (int j = 0; j < 4; ++j) {
                L[2 * j]     = tanh2(pack_f16x2(d[j][0], d[j][1]));
                L[2 * j + 1] = tanh2(pack_f16x2(d[j][2], d[j][3]));
            }
            if (g < 4) {                                 // thread-private stash (no sync needed)
                *(uint4*)(stash + g * 32)      = make_uint4(L[0], L[1], L[2], L[3]);
                *(uint4*)(stash + g * 32 + 16) = make_uint4(L[4], L[5], L[6], L[7]);
            } else {
                #pragma unroll
                for (int j = 0; j < 8; ++j) held[(g - 4) * 8 + j] = L[j];
            }
        }
        // commit next-step A fragments (LDS first so latency overlaps the reg moves)
        uint4 v[8];
        #pragma unroll
        for (int i = 0; i < 8; ++i) v[i] = *(const uint4*)(stash + i * 16);
        #pragma unroll
        for (int i = 0; i < 8; ++i) {
            hA[4 * i] = v[i].x; hA[4 * i + 1] = v[i].y;
            hA[4 * i + 2] = v[i].z; hA[4 * i + 3] = v[i].w;
        }
        #pragma unroll
        for (int i = 0; i < 32; ++i) hA[32 + i] = held[i];
    }

    // ---- head: stage W1 into dead stash, hidden = relu(h@W1+b1), W2 + softmax ----
    __syncthreads();
    for (int i = tid; i < Hn * 64; i += NT) {            // W1[k][n]
        int k = i >> 6, n = i & 63;
        *(__half*)(smem + OFF_STASH + k * W1_STRIDE + n * 2) = __float2half(gW1[i]);
    }
    __syncthreads();
    const uint32_t lds_w1 = sb + OFF_STASH
        + ((tq & 1) * 8 + (lane & 7)) * W1_STRIDE + (tq >> 1) * 16;

    float hd[8][4];
    #pragma unroll
    for (int t2 = 0; t2 < 8; ++t2)
        hd[t2][0] = hd[t2][1] = hd[t2][2] = hd[t2][3] = 0.f;
    #pragma unroll
    for (int kc = 0; kc < 16; ++kc) {
        const uint32_t a0 = hA[4 * kc], a1 = hA[4 * kc + 1];
        const uint32_t a2 = hA[4 * kc + 2], a3 = hA[4 * kc + 3];
        const uint32_t base = lds_w1 + kc * 16 * W1_STRIDE;
        #pragma unroll
        for (int nt2 = 0; nt2 < 4; ++nt2) {
            uint32_t b0, b1, b2, b3;
            ldsm4t(b0, b1, b2, b3, base + nt2 * 32);
            mma16816(hd[2 * nt2],     a0, a1, a2, a3, b0, b1);
            mma16816(hd[2 * nt2 + 1], a0, a1, a2, a3, b2, b3);
        }
    }
    {
        const float* sb1 = (const float*)(smem + OFF_B1);
        const float* sw2 = (const float*)(smem + OFF_W2);
        const float* sb2 = (const float*)(smem + OFF_B2);
        float acc0[5] = {0, 0, 0, 0, 0}, acc8[5] = {0, 0, 0, 0, 0};
        #pragma unroll
        for (int t2 = 0; t2 < 8; ++t2) {
            int c0 = 8 * t2 + 2 * tig;
            float b1a = sb1[c0], b1b = sb1[c0 + 1];
            float h00 = fmaxf(hd[t2][0] + b1a, 0.f), h01 = fmaxf(hd[t2][1] + b1b, 0.f);
            float h80 = fmaxf(hd[t2][2] + b1a, 0.f), h81 = fmaxf(hd[t2][3] + b1b, 0.f);
            #pragma unroll
            for (int c = 0; c < 5; ++c) {
                acc0[c] = fmaf(h00, sw2[c0 * 5 + c], fmaf(h01, sw2[(c0 + 1) * 5 + c], acc0[c]));
                acc8[c] = fmaf(h80, sw2[c0 * 5 + c], fmaf(h81, sw2[(c0 + 1) * 5 + c], acc8[c]));
            }
        }
        #pragma unroll
        for (int c = 0; c < 5; ++c) {                    // reduce over 4-lane tig group
            acc0[c] += __shfl_xor_sync(0xFFFFFFFFu, acc0[c], 1);
            acc0[c] += __shfl_xor_sync(0xFFFFFFFFu, acc0[c], 2);
            acc8[c] += __shfl_xor_sync(0xFFFFFFFFu, acc8[c], 1);
            acc8[c] += __shfl_xor_sync(0xFFFFFFFFu, acc8[c], 2);
        }
        if (tig == 0) {
            float o[5];
            if (row0 < Bn) {
                #pragma unroll
                for (int c = 0; c < 5; ++c) o[c] = acc0[c] + sb2[c];
                float mx = fmaxf(fmaxf(fmaxf(o[0], o[1]), fmaxf(o[2], o[3])), o[4]);
                float s = 0.f;
                #pragma unroll
                for (int c = 0; c < 5; ++c) { o[c] = __expf(o[c] - mx); s += o[c]; }
                float inv = 1.f / s;
                #pragma unroll
                for (int c = 0; c < 5; ++c) gout[(size_t)row0 * 5 + c] = o[c] * inv;
            }
            if (row0 + 8 < Bn) {
                #pragma unroll
                for (int c = 0; c < 5; ++c) o[c] = acc8[c] + sb2[c];
                float mx = fmaxf(fmaxf(fmaxf(o[0], o[1]), fmaxf(o[2], o[3])), o[4]);
                float s = 0.f;
                #pragma unroll
                for (int c = 0; c < 5; ++c) { o[c] = __expf(o[c] - mx); s += o[c]; }
                float inv = 1.f / s;
                #pragma unroll
                for (int c = 0; c < 5; ++c) gout[(size_t)(row0 + 8) * 5 + c] = o[c] * inv;
            }
        }
    }
}

// ---------------- launch ----------------
extern "C" void kernel_launch(void* const* d_in, const int* in_sizes, int n_in,
                              void* d_out, int out_size) {
    const float* x  = (const float*)d_in[0];
    const float* Wx = (const float*)d_in[1];
    const float* Wh = (const float*)d_in[2];
    const float* br = (const float*)d_in[3];
    const float* W1 = (const float*)d_in[4];
    const float* b1 = (const float*)d_in[5];
    const float* W2 = (const float*)d_in[6];
    const float* b2 = (const float*)d_in[7];

    cudaFuncSetAttribute(rnn_kernel, cudaFuncAttributeMaxDynamicSharedMemorySize, SMEM_TOTAL);
    const int grid = (Bn + BM - 1) / BM;   // 147 CTAs -> single wave on 148 SMs
    rnn_kernel<<<grid, NT, SMEM_TOTAL>>>(x, Wx, Wh, br, W1, b1, W2, b2, (float*)d_out);
}

// round 14
// speedup vs baseline: 1.0289x; 1.0289x over previous
#include <cuda_runtime.h>
#include <cuda_fp16.h>
#include <cstdint>

#define DINL __device__ __forceinline__

namespace {
constexpr int Bn = 32768;
constexpr int Tn = 187;
constexpr int Hn = 256;
constexpr int BM = 224;          // batch rows per CTA -> 147 CTAs = ONE wave on 148 SMs
constexpr int NT = 224;          // 7 warps x 32 rows each (M=32 per warp)

constexpr int WH_STRIDE = 528;   // bytes per Wh row (264 f16) -> conflict-free ldsm
constexpr int W1_STRIDE = 144;   // bytes per W1 row (72 f16)
constexpr int ST_STRIDE = 400;   // per-thread stash stride (100 u32; 96 used) -> 25 chunks,
                                 // odd multiplier mod 32 -> conflict-free STS/LDS.128

constexpr int OFF_WH    = 0;                          // 256*528 = 135168
constexpr int OFF_STASH = OFF_WH + Hn * WH_STRIDE;    // 135168, 224*400 = 89600 (W1 later)
constexpr int OFF_WXB   = OFF_STASH + NT * ST_STRIDE; // 224768, float2{Wx,b} x256
constexpr int OFF_B1    = OFF_WXB + Hn * 8;           // 226816
constexpr int OFF_W2    = OFF_B1 + 64 * 4;            // 227072
constexpr int OFF_B2    = OFF_W2 + 320 * 4;           // 228352
constexpr int SMEM_TOTAL = OFF_B2 + 32;               // 228384
static_assert(SMEM_TOTAL <= 232448, "smem overflow");
static_assert(Hn * W1_STRIDE <= NT * ST_STRIDE, "W1 must fit in stash");
}

// ---------------- helpers ----------------
DINL uint32_t smem_u32(const void* p) {
    uint32_t a;
    asm("{ .reg .u64 t; cvta.to.shared.u64 t, %1; cvt.u32.u64 %0, t; }" : "=r"(a) : "l"(p));
    return a;
}
DINL void ldsm4t(uint32_t& r0, uint32_t& r1, uint32_t& r2, uint32_t& r3, uint32_t addr) {
    asm volatile("ldmatrix.sync.aligned.m8n8.x4.trans.shared.b16 {%0,%1,%2,%3}, [%4];"
                 : "=r"(r0), "=r"(r1), "=r"(r2), "=r"(r3) : "r"(addr));
}
DINL void mma16816(float* d, uint32_t a0, uint32_t a1, uint32_t a2, uint32_t a3,
                   uint32_t b0, uint32_t b1) {
    asm volatile("mma.sync.aligned.m16n8k16.row.col.f32.f16.f16.f32 "
                 "{%0,%1,%2,%3}, {%4,%5,%6,%7}, {%8,%9}, {%0,%1,%2,%3};"
                 : "+f"(d[0]), "+f"(d[1]), "+f"(d[2]), "+f"(d[3])
                 : "r"(a0), "r"(a1), "r"(a2), "r"(a3), "r"(b0), "r"(b1));
}
DINL uint32_t pack_f16x2(float lo, float hi) {
    uint32_t r;
    asm("cvt.rn.f16x2.f32 %0, %1, %2;" : "=r"(r) : "f"(hi), "f"(lo));
    return r;
}
DINL uint32_t tanh2(uint32_t v) {
    uint32_t r;
    asm("tanh.approx.f16x2 %0, %1;" : "=r"(r) : "r"(v));
    return r;
}

// ---------------- kernel ----------------
__global__ void __launch_bounds__(NT, 1)
rnn_kernel(const float* __restrict__ gx,  const float* __restrict__ gWx,
           const float* __restrict__ gWh, const float* __restrict__ gbr,
           const float* __restrict__ gW1, const float* __restrict__ gb1,
           const float* __restrict__ gW2, const float* __restrict__ gb2,
           float* __restrict__ gout) {
    extern __shared__ char smem[];
    const int tid  = threadIdx.x;
    const int lane = tid & 31;
    const int wid  = tid >> 5;       // 0..6
    const int m0   = blockIdx.x * BM;
    const int gid  = lane >> 2;      // row group 0..7
    const int tig  = lane & 3;       // thread-in-group

    // ---- cooperative staging (Wh + consts; x streams from L2 via LDG) ----
    for (int i = tid; i < Hn * Hn; i += NT) {            // Wh[k][n] -> k-major padded f16
        int k = i >> 8, n = i & 255;
        *(__half*)(smem + OFF_WH + k * WH_STRIDE + n * 2) = __float2half(gWh[i]);
    }
    for (int i = tid; i < Hn; i += NT)
        ((float2*)(smem + OFF_WXB))[i] = make_float2(gWx[i], gbr[i]);
    for (int i = tid; i < 64; i += NT)  ((float*)(smem + OFF_B1))[i] = gb1[i];
    for (int i = tid; i < 320; i += NT) ((float*)(smem + OFF_W2))[i] = gW2[i];
    if (tid < 5) ((float*)(smem + OFF_B2))[tid] = gb2[tid];
    __syncthreads();

    // ---- per-warp setup ----
    const uint32_t sb = smem_u32(smem);
    const int tq = lane >> 3;   // ldmatrix x4 slot
    const uint32_t lds_wh = sb + OFF_WH + ((tq & 1) * 8 + (lane & 7)) * WH_STRIDE + (tq >> 1) * 16;
    char* stash = smem + OFF_STASH + tid * ST_STRIDE;    // thread-private carry stash
    const float4* wxb4 = (const float4*)(smem + OFF_WXB);   // {w0,b0,w1,b1} per even col pair

    // this thread's 4 batch rows: base + {0,8,16,24}
    const int row0 = m0 + wid * 32 + gid;
    size_t roff[4];
    #pragma unroll
    for (int j = 0; j < 4; ++j) {
        int r = row0 + 8 * j;
        roff[j] = (size_t)(r < Bn ? r : Bn - 1) * Tn;    // clamped for LDG
    }

    // hA[8kc+j]: j=0..3 m-tile0 (rows gid,gid+8), j=4..7 m-tile1 (rows gid+16,gid+24).
    // Within each quad: {row, row+8} x {k8 block 2kc, 2kc+1}, col pair 2tig.
    uint32_t hA[128];

    // ---- t = 0: h0 = tanh(x0*Wx + b) ----
    {
        float xv[4];
        #pragma unroll
        for (int j = 0; j < 4; ++j) xv[j] = gx[roff[j]];
        #pragma unroll
        for (int t2 = 0; t2 < 32; ++t2) {                // t2 = k8 block
            float4 wb = wxb4[4 * t2 + tig];
            int idx = 8 * (t2 >> 1) + (t2 & 1) * 2;
            hA[idx]     = tanh2(pack_f16x2(fmaf(xv[0], wb.x, wb.y), fmaf(xv[0], wb.z, wb.w)));
            hA[idx + 1] = tanh2(pack_f16x2(fmaf(xv[1], wb.x, wb.y), fmaf(xv[1], wb.z, wb.w)));
            hA[idx + 4] = tanh2(pack_f16x2(fmaf(xv[2], wb.x, wb.y), fmaf(xv[2], wb.z, wb.w)));
            hA[idx + 5] = tanh2(pack_f16x2(fmaf(xv[3], wb.x, wb.y), fmaf(xv[3], wb.z, wb.w)));
        }
    }
    float xn[4];
    #pragma unroll
    for (int j = 0; j < 4; ++j) xn[j] = gx[roff[j] + 1];

    // ---- recurrence: t = 1..186 (warp-private, no sync) ----
    #pragma unroll 1
    for (int t = 1; t < Tn; ++t) {
        float xv[4];
        #pragma unroll
        for (int j = 0; j < 4; ++j) xv[j] = xn[j];
        const int tnext = (t + 1 < Tn) ? t + 1 : t;      // prefetch next step's x (L2-resident)
        #pragma unroll
        for (int j = 0; j < 4; ++j) xn[j] = gx[roff[j] + tnext];

        uint32_t held[32];                               // reg carry for groups 6,7
        #pragma unroll
        for (int g = 0; g < 8; ++g) {                    // 32-col n-group: n8-tiles 4g..4g+3
            float d0[4][4], d1[4][4];
            #pragma unroll
            for (int q = 0; q < 4; ++q) {                // D init = x_t*Wx + b
                float4 wb = wxb4[16 * g + 4 * q + tig];
                d0[q][0] = fmaf(xv[0], wb.x, wb.y); d0[q][1] = fmaf(xv[0], wb.z, wb.w);
                d0[q][2] = fmaf(xv[1], wb.x, wb.y); d0[q][3] = fmaf(xv[1], wb.z, wb.w);
                d1[q][0] = fmaf(xv[2], wb.x, wb.y); d1[q][1] = fmaf(xv[2], wb.z, wb.w);
                d1[q][2] = fmaf(xv[3], wb.x, wb.y); d1[q][3] = fmaf(xv[3], wb.z, wb.w);
            }
            #pragma unroll
            for (int kc = 0; kc < 16; ++kc) {
                const uint32_t a0 = hA[8 * kc],     a1 = hA[8 * kc + 1];
                const uint32_t a2 = hA[8 * kc + 2], a3 = hA[8 * kc + 3];
                const uint32_t a4 = hA[8 * kc + 4], a5 = hA[8 * kc + 5];
                const uint32_t a6 = hA[8 * kc + 6], a7 = hA[8 * kc + 7];
                const uint32_t base = lds_wh + kc * 16 * WH_STRIDE + g * 64;
                #pragma unroll
                for (int q = 0; q < 2; ++q) {            // one ldsm.x4 feeds 4 MMAs
                    uint32_t b0, b1, b2, b3;
                    ldsm4t(b0, b1, b2, b3, base + q * 32);
                    mma16816(d0[2 * q],     a0, a1, a2, a3, b0, b1);
                    mma16816(d0[2 * q + 1], a0, a1, a2, a3, b2, b3);
                    mma16816(d1[2 * q],     a4, a5, a6, a7, b0, b1);
                    mma16816(d1[2 * q + 1], a4, a5, a6, a7, b2, b3);
                }
            }
            // pack -> tanh -> hA-order block 16g..16g+15
            uint32_t L[16];
            #pragma unroll
            for (int q = 0; q < 4; ++q) {
                int base = 8 * (q >> 1) + 2 * (q & 1);
                L[base]     = tanh2(pack_f16x2(d0[q][0], d0[q][1]));
                L[base + 1] = tanh2(pack_f16x2(d0[q][2], d0[q][3]));
                L[base + 4] = tanh2(pack_f16x2(d1[q][0], d1[q][1]));
                L[base + 5] = tanh2(pack_f16x2(d1[q][2], d1[q][3]));
            }
            if (g < 6) {                                 // thread-private stash (no sync needed)
                #pragma unroll
                for (int c = 0; c < 4; ++c)
                    *(uint4*)(stash + g * 64 + c * 16) =
                        make_uint4(L[4 * c], L[4 * c + 1], L[4 * c + 2], L[4 * c + 3]);
            } else {
                #pragma unroll
                for (int j = 0; j < 16; ++j) held[(g - 6) * 16 + j] = L[j];
            }
        }
        // commit next-step A fragments (LDS first so latency overlaps the reg moves)
        #pragma unroll
        for (int i = 0; i < 24; ++i) {
            uint4 v = *(const uint4*)(stash + i * 16);
            hA[4 * i] = v.x; hA[4 * i + 1] = v.y; hA[4 * i + 2] = v.z; hA[4 * i + 3] = v.w;
        }
        #pragma unroll
        for (int i = 0; i < 32; ++i) hA[96 + i] = held[i];
    }

    // ---- head: stage W1 into dead stash, hidden = relu(h@W1+b1), W2 + softmax ----
    __syncthreads();
    for (int i = tid; i < Hn * 64; i += NT) {            // W1[k][n]
        int k = i >> 6, n = i & 63;
        *(__half*)(smem + OFF_STASH + k * W1_STRIDE + n * 2) = __float2half(gW1[i]);
    }
    __syncthreads();
    const uint32_t lds_w1 = sb + OFF_STASH
        + ((tq & 1) * 8 + (lane & 7)) * W1_STRIDE + (tq >> 1) * 16;

    float hd0[8][4], hd1[8][4];
    #pragma unroll
    for (int t2 = 0; t2 < 8; ++t2)
        #pragma unroll
        for (int c = 0; c < 4; ++c) { hd0[t2][c] = 0.f; hd1[t2][c] = 0.f; }
    #pragma unroll
    for (int kc = 0; kc < 16; ++kc) {
        const uint32_t a0 = hA[8 * kc],     a1 = hA[8 * kc + 1];
        const uint32_t a2 = hA[8 * kc + 2], a3 = hA[8 * kc + 3];
        const uint32_t a4 = hA[8 * kc + 4], a5 = hA[8 * kc + 5];
        const uint32_t a6 = hA[8 * kc + 6], a7 = hA[8 * kc + 7];
        const uint32_t base = lds_w1 + kc * 16 * W1_STRIDE;
        #pragma unroll
        for (int nt2 = 0; nt2 < 4; ++nt2) {
            uint32_t b0, b1, b2, b3;
            ldsm4t(b0, b1, b2, b3, base + nt2 * 32);
            mma16816(hd0[2 * nt2],     a0, a1, a2, a3, b0, b1);
            mma16816(hd0[2 * nt2 + 1], a0, a1, a2, a3, b2, b3);
            mma16816(hd1[2 * nt2],     a4, a5, a6, a7, b0, b1);
            mma16816(hd1[2 * nt2 + 1], a4, a5, a6, a7, b2, b3);
        }
    }
    {
        const float* sb1 = (const float*)(smem + OFF_B1);
        const float* sw2 = (const float*)(smem + OFF_W2);
        const float* sb2 = (const float*)(smem + OFF_B2);
        float acc[4][5];
        #pragma unroll
        for (int j = 0; j < 4; ++j)
            #pragma unroll
            for (int c = 0; c < 5; ++c) acc[j][c] = 0.f;
        #pragma unroll
        for (int t2 = 0; t2 < 8; ++t2) {
            int c0 = 8 * t2 + 2 * tig;
            float b1a = sb1[c0], b1b = sb1[c0 + 1];
            float hv[4][2] = {
                { fmaxf(hd0[t2][0] + b1a, 0.f), fmaxf(hd0[t2][1] + b1b, 0.f) },
                { fmaxf(hd0[t2][2] + b1a, 0.f), fmaxf(hd0[t2][3] + b1b, 0.f) },
                { fmaxf(hd1[t2][0] + b1a, 0.f), fmaxf(hd1[t2][1] + b1b, 0.f) },
                { fmaxf(hd1[t2][2] + b1a, 0.f), fmaxf(hd1[t2][3] + b1b, 0.f) } };
            #pragma unroll
            for (int j = 0; j < 4; ++j)
                #pragma unroll
                for (int c = 0; c < 5; ++c)
                    acc[j][c] = fmaf(hv[j][0], sw2[c0 * 5 + c],
                               fmaf(hv[j][1], sw2[(c0 + 1) * 5 + c], acc[j][c]));
        }
        #pragma unroll
        for (int j = 0; j < 4; ++j)
            #pragma unroll
            for (int c = 0; c < 5; ++c) {                // reduce over 4-lane tig group
                acc[j][c] += __shfl_xor_sync(0xFFFFFFFFu, acc[j][c], 1);
                acc[j][c] += __shfl_xor_sync(0xFFFFFFFFu, acc[j][c], 2);
            }
        if (tig == 0) {
            #pragma unroll
            for (int j = 0; j < 4; ++j) {
                int r = row0 + 8 * j;
                if (r < Bn) {
                    float o[5];
                    #pragma unroll
                    for (int c = 0; c < 5; ++c) o[c] = acc[j][c] + sb2[c];
                    float mx = fmaxf(fmaxf(fmaxf(o[0], o[1]), fmaxf(o[2], o[3])), o[4]);
                    float s = 0.f;
                    #pragma unroll
                    for (int c = 0; c < 5; ++c) { o[c] = __expf(o[c] - mx); s += o[c]; }
                    float inv = 1.f / s;
                    #pragma unroll
                    for (int c = 0; c < 5; ++c) gout[(size_t)r * 5 + c] = o[c] * inv;
                }
            }
        }
    }
}

// ---------------- launch ----------------
extern "C" void kernel_launch(void* const* d_in, const int* in_sizes, int n_in,
                              void* d_out, int out_size) {
    const float* x  = (const float*)d_in[0];
    const float* Wx = (const float*)d_in[1];
    const float* Wh = (const float*)d_in[2];
    const float* br = (const float*)d_in[3];
    const float* W1 = (const float*)d_in[4];
    const float* b1 = (const float*)d_in[5];
    const float* W2 = (const float*)d_in[6];
    const float* b2 = (const float*)d_in[7];

    cudaFuncSetAttribute(rnn_kernel, cudaFuncAttributeMaxDynamicSharedMemorySize, SMEM_TOTAL);
    const int grid = (Bn + BM - 1) / BM;   // 147 CTAs -> single wave on 148 SMs
    rnn_kernel<<<grid, NT, SMEM_TOTAL>>>(x, Wx, Wh, br, W1, b1, W2, b2, (float*)d_out);
}

// round 15
// speedup vs baseline: 1.0806x; 1.0503x over previous
#include <cuda_runtime.h>
#include <cuda_fp16.h>
#include <cstdint>

#define DINL __device__ __forceinline__

namespace {
constexpr int Bn = 32768;
constexpr int Tn = 187;
constexpr int Hn = 256;
constexpr int BM = 224;          // batch rows per CTA -> 147 CTAs = ONE wave on 148 SMs
constexpr int NT = 224;          // 7 warps x 32 rows each (M=32 per warp)

constexpr int WH_STRIDE = 528;   // bytes per Wh row (264 f16) -> conflict-free ldsm
constexpr int W1_STRIDE = 144;   // bytes per W1 row (72 f16)
constexpr int ST_STRIDE = 400;   // per-thread stash stride (100 u32; 96 used) -> 25 chunks,
                                 // odd multiplier mod 32 -> conflict-free STS/LDS.128

constexpr int OFF_WH    = 0;                          // 256*528 = 135168
constexpr int OFF_STASH = OFF_WH + Hn * WH_STRIDE;    // 135168, 224*400 = 89600 (W1 later)
constexpr int OFF_WXB   = OFF_STASH + NT * ST_STRIDE; // 224768, float2{Wx,b} x256
constexpr int OFF_B1    = OFF_WXB + Hn * 8;           // 226816
constexpr int OFF_W2    = OFF_B1 + 64 * 4;            // 227072
constexpr int OFF_B2    = OFF_W2 + 320 * 4;           // 228352
constexpr int SMEM_TOTAL = OFF_B2 + 32;               // 228384
static_assert(SMEM_TOTAL <= 232448, "smem overflow");
static_assert(Hn * W1_STRIDE <= NT * ST_STRIDE, "W1 must fit in stash");
}

// ---------------- helpers ----------------
DINL uint32_t smem_u32(const void* p) {
    uint32_t a;
    asm("{ .reg .u64 t; cvta.to.shared.u64 t, %1; cvt.u32.u64 %0, t; }" : "=r"(a) : "l"(p));
    return a;
}
DINL void ldsm4t(uint32_t& r0, uint32_t& r1, uint32_t& r2, uint32_t& r3, uint32_t addr) {
    asm volatile("ldmatrix.sync.aligned.m8n8.x4.trans.shared.b16 {%0,%1,%2,%3}, [%4];"
                 : "=r"(r0), "=r"(r1), "=r"(r2), "=r"(r3) : "r"(addr));
}
DINL void mma16816(float* d, uint32_t a0, uint32_t a1, uint32_t a2, uint32_t a3,
                   uint32_t b0, uint32_t b1) {
    asm volatile("mma.sync.aligned.m16n8k16.row.col.f32.f16.f16.f32 "
                 "{%0,%1,%2,%3}, {%4,%5,%6,%7}, {%8,%9}, {%0,%1,%2,%3};"
                 : "+f"(d[0]), "+f"(d[1]), "+f"(d[2]), "+f"(d[3])
                 : "r"(a0), "r"(a1), "r"(a2), "r"(a3), "r"(b0), "r"(b1));
}
DINL uint32_t pack_f16x2(float lo, float hi) {
    uint32_t r;
    asm("cvt.rn.f16x2.f32 %0, %1, %2;" : "=r"(r) : "f"(hi), "f"(lo));
    return r;
}
DINL uint32_t tanh2(uint32_t v) {
    uint32_t r;
    asm("tanh.approx.f16x2 %0, %1;" : "=r"(r) : "r"(v));
    return r;
}

// ---------------- kernel ----------------
__global__ void __launch_bounds__(NT, 1)
rnn_kernel(const float* __restrict__ gx,  const float* __restrict__ gWx,
           const float* __restrict__ gWh, const float* __restrict__ gbr,
           const float* __restrict__ gW1, const float* __restrict__ gb1,
           const float* __restrict__ gW2, const float* __restrict__ gb2,
           float* __restrict__ gout) {
    extern __shared__ char smem[];
    const int tid  = threadIdx.x;
    const int lane = tid & 31;
    const int wid  = tid >> 5;       // 0..6
    const int m0   = blockIdx.x * BM;
    const int gid  = lane >> 2;      // row group 0..7
    const int tig  = lane & 3;       // thread-in-group

    // ---- cooperative staging (Wh + consts; x streams from L2 via LDG) ----
    for (int i = tid; i < Hn * Hn; i += NT) {            // Wh[k][n] -> k-major padded f16
        int k = i >> 8, n = i & 255;
        *(__half*)(smem + OFF_WH + k * WH_STRIDE + n * 2) = __float2half(gWh[i]);
    }
    for (int i = tid; i < Hn; i += NT)
        ((float2*)(smem + OFF_WXB))[i] = make_float2(gWx[i], gbr[i]);
    for (int i = tid; i < 64; i += NT)  ((float*)(smem + OFF_B1))[i] = gb1[i];
    for (int i = tid; i < 320; i += NT) ((float*)(smem + OFF_W2))[i] = gW2[i];
    if (tid < 5) ((float*)(smem + OFF_B2))[tid] = gb2[tid];
    __syncthreads();

    // ---- per-warp setup ----
    const uint32_t sb = smem_u32(smem);
    const int tq = lane >> 3;   // ldmatrix x4 slot
    const uint32_t lds_wh = sb + OFF_WH + ((tq & 1) * 8 + (lane & 7)) * WH_STRIDE + (tq >> 1) * 16;
    char* stash = smem + OFF_STASH + tid * ST_STRIDE;    // thread-private carry stash
    const float4* wxb4 = (const float4*)(smem + OFF_WXB);   // {w0,b0,w1,b1} per even col pair

    // this thread's 4 batch rows: base + {0,8,16,24}
    const int row0 = m0 + wid * 32 + gid;
    size_t roff[4];
    #pragma unroll
    for (int j = 0; j < 4; ++j) {
        int r = row0 + 8 * j;
        roff[j] = (size_t)(r < Bn ? r : Bn - 1) * Tn;    // clamped for LDG
    }

    // hA[8kc+j]: j=0..3 m-tile0 (rows gid,gid+8), j=4..7 m-tile1 (rows gid+16,gid+24).
    // Within each quad: {row, row+8} x {k8 block 2kc, 2kc+1}, col pair 2tig.
    uint32_t hA[128];

    // ---- t = 0: h0 = tanh(x0*Wx + b) ----
    {
        float xv[4];
        #pragma unroll
        for (int j = 0; j < 4; ++j) xv[j] = gx[roff[j]];
        #pragma unroll
        for (int t2 = 0; t2 < 32; ++t2) {                // t2 = k8 block
            float4 wb = wxb4[4 * t2 + tig];
            int idx = 8 * (t2 >> 1) + (t2 & 1) * 2;
            hA[idx]     = tanh2(pack_f16x2(fmaf(xv[0], wb.x, wb.y), fmaf(xv[0], wb.z, wb.w)));
            hA[idx + 1] = tanh2(pack_f16x2(fmaf(xv[1], wb.x, wb.y), fmaf(xv[1], wb.z, wb.w)));
            hA[idx + 4] = tanh2(pack_f16x2(fmaf(xv[2], wb.x, wb.y), fmaf(xv[2], wb.z, wb.w)));
            hA[idx + 5] = tanh2(pack_f16x2(fmaf(xv[3], wb.x, wb.y), fmaf(xv[3], wb.z, wb.w)));
        }
    }
    float xn[4];
    #pragma unroll
    for (int j = 0; j < 4; ++j) xn[j] = gx[roff[j] + 1];

    // ---- recurrence: t = 1..186 (warp-private, no sync) ----
    #pragma unroll 1
    for (int t = 1; t < Tn; ++t) {
        float xv[4];
        #pragma unroll
        for (int j = 0; j < 4; ++j) xv[j] = xn[j];
        const int tnext = (t + 1 < Tn) ? t + 1 : t;      // prefetch next step's x (L2-resident)
        #pragma unroll
        for (int j = 0; j < 4; ++j) xn[j] = gx[roff[j] + tnext];

        uint32_t held[32];                               // reg carry for groups 12..15
        #pragma unroll
        for (int g = 0; g < 16; ++g) {                   // 16-col n-group: n8-tiles 2g, 2g+1
            float d0[2][4], d1[2][4];
            #pragma unroll
            for (int j = 0; j < 2; ++j) {                // D init = x_t*Wx + b
                float4 wb = wxb4[8 * g + 4 * j + tig];
                d0[j][0] = fmaf(xv[0], wb.x, wb.y); d0[j][1] = fmaf(xv[0], wb.z, wb.w);
                d0[j][2] = fmaf(xv[1], wb.x, wb.y); d0[j][3] = fmaf(xv[1], wb.z, wb.w);
                d1[j][0] = fmaf(xv[2], wb.x, wb.y); d1[j][1] = fmaf(xv[2], wb.z, wb.w);
                d1[j][2] = fmaf(xv[3], wb.x, wb.y); d1[j][3] = fmaf(xv[3], wb.z, wb.w);
            }
            // kc loop, B double-buffered: prefetch kc+1 while kc's 4 MMAs issue
            uint32_t bb[2][4];
            ldsm4t(bb[0][0], bb[0][1], bb[0][2], bb[0][3], lds_wh + g * 32);
            #pragma unroll
            for (int kc = 0; kc < 16; ++kc) {
                const int cur = kc & 1;
                if (kc < 15)
                    ldsm4t(bb[cur ^ 1][0], bb[cur ^ 1][1], bb[cur ^ 1][2], bb[cur ^ 1][3],
                           lds_wh + (kc + 1) * 16 * WH_STRIDE + g * 32);
                const uint32_t a0 = hA[8 * kc],     a1 = hA[8 * kc + 1];
                const uint32_t a2 = hA[8 * kc + 2], a3 = hA[8 * kc + 3];
                const uint32_t a4 = hA[8 * kc + 4], a5 = hA[8 * kc + 5];
                const uint32_t a6 = hA[8 * kc + 6], a7 = hA[8 * kc + 7];
                mma16816(d0[0], a0, a1, a2, a3, bb[cur][0], bb[cur][1]);
                mma16816(d0[1], a0, a1, a2, a3, bb[cur][2], bb[cur][3]);
                mma16816(d1[0], a4, a5, a6, a7, bb[cur][0], bb[cur][1]);
                mma16816(d1[1], a4, a5, a6, a7, bb[cur][2], bb[cur][3]);
            }
            // pack -> tanh -> hA slots [8g : 8g+8) for next step
            uint32_t L[8];
            #pragma unroll
            for (int j = 0; j < 2; ++j) {
                L[2 * j]     = tanh2(pack_f16x2(d0[j][0], d0[j][1]));
                L[2 * j + 1] = tanh2(pack_f16x2(d0[j][2], d0[j][3]));
                L[2 * j + 4] = tanh2(pack_f16x2(d1[j][0], d1[j][1]));
                L[2 * j + 5] = tanh2(pack_f16x2(d1[j][2], d1[j][3]));
            }
            if (g < 12) {                                // thread-private stash (no sync needed)
                *(uint4*)(stash + g * 32)      = make_uint4(L[0], L[1], L[2], L[3]);
                *(uint4*)(stash + g * 32 + 16) = make_uint4(L[4], L[5], L[6], L[7]);
            } else {
                #pragma unroll
                for (int j = 0; j < 8; ++j) held[(g - 12) * 8 + j] = L[j];
            }
        }
        // commit next-step A fragments (LDS first so latency overlaps the reg moves)
        #pragma unroll
        for (int i = 0; i < 24; ++i) {
            uint4 v = *(const uint4*)(stash + i * 16);
            hA[4 * i] = v.x; hA[4 * i + 1] = v.y; hA[4 * i + 2] = v.z; hA[4 * i + 3] = v.w;
        }
        #pragma unroll
        for (int i = 0; i < 32; ++i) hA[96 + i] = held[i];
    }

    // ---- head: stage W1 into dead stash, hidden = relu(h@W1+b1), W2 + softmax ----
    __syncthreads();
    for (int i = tid; i < Hn * 64; i += NT) {            // W1[k][n]
        int k = i >> 6, n = i & 63;
        *(__half*)(smem + OFF_STASH + k * W1_STRIDE + n * 2) = __float2half(gW1[i]);
    }
    __syncthreads();
    const uint32_t lds_w1 = sb + OFF_STASH
        + ((tq & 1) * 8 + (lane & 7)) * W1_STRIDE + (tq >> 1) * 16;

    float hd0[8][4], hd1[8][4];
    #pragma unroll
    for (int t2 = 0; t2 < 8; ++t2)
        #pragma unroll
        for (int c = 0; c < 4; ++c) { hd0[t2][c] = 0.f; hd1[t2][c] = 0.f; }
    #pragma unroll
    for (int kc = 0; kc < 16; ++kc) {
        const uint32_t a0 = hA[8 * kc],     a1 = hA[8 * kc + 1];
        const uint32_t a2 = hA[8 * kc + 2], a3 = hA[8 * kc + 3];
        const uint32_t a4 = hA[8 * kc + 4], a5 = hA[8 * kc + 5];
        const uint32_t a6 = hA[8 * kc + 6], a7 = hA[8 * kc + 7];
        const uint32_t base = lds_w1 + kc * 16 * W1_STRIDE;
        #pragma unroll
        for (int nt2 = 0; nt2 < 4; ++nt2) {
            uint32_t b0, b1, b2, b3;
            ldsm4t(b0, b1, b2, b3, base + nt2 * 32);
            mma16816(hd0[2 * nt2],     a0, a1, a2, a3, b0, b1);
            mma16816(hd0[2 * nt2 + 1], a0, a1, a2, a3, b2, b3);
            mma16816(hd1[2 * nt2],     a4, a5, a6, a7, b0, b1);
            mma16816(hd1[2 * nt2 + 1], a4, a5, a6, a7, b2, b3);
        }
    }
    {
        const float* sb1 = (const float*)(smem + OFF_B1);
        const float* sw2 = (const float*)(smem + OFF_W2);
        const float* sb2 = (const float*)(smem + OFF_B2);
        float acc[4][5];
        #pragma unroll
        for (int j = 0; j < 4; ++j)
            #pragma unroll
            for (int c = 0; c < 5; ++c) acc[j][c] = 0.f;
        #pragma unroll
        for (int t2 = 0; t2 < 8; ++t2) {
            int c0 = 8 * t2 + 2 * tig;
            float b1a = sb1[c0], b1b = sb1[c0 + 1];
            float hv[4][2] = {
                { fmaxf(hd0[t2][0] + b1a, 0.f), fmaxf(hd0[t2][1] + b1b, 0.f) },
                { fmaxf(hd0[t2][2] + b1a, 0.f), fmaxf(hd0[t2][3] + b1b, 0.f) },
                { fmaxf(hd1[t2][0] + b1a, 0.f), fmaxf(hd1[t2][1] + b1b, 0.f) },
                { fmaxf(hd1[t2][2] + b1a, 0.f), fmaxf(hd1[t2][3] + b1b, 0.f) } };
            #pragma unroll
            for (int j = 0; j < 4; ++j)
                #pragma unroll
                for (int c = 0; c < 5; ++c)
                    acc[j][c] = fmaf(hv[j][0], sw2[c0 * 5 + c],
                               fmaf(hv[j][1], sw2[(c0 + 1) * 5 + c], acc[j][c]));
        }
        #pragma unroll
        for (int j = 0; j < 4; ++j)
            #pragma unroll
            for (int c = 0; c < 5; ++c) {                // reduce over 4-lane tig group
                acc[j][c] += __shfl_xor_sync(0xFFFFFFFFu, acc[j][c], 1);
                acc[j][c] += __shfl_xor_sync(0xFFFFFFFFu, acc[j][c], 2);
            }
        if (tig == 0) {
            #pragma unroll
            for (int j = 0; j < 4; ++j) {
                int r = row0 + 8 * j;
                if (r < Bn) {
                    float o[5];
                    #pragma unroll
                    for (int c = 0; c < 5; ++c) o[c] = acc[j][c] + sb2[c];
                    float mx = fmaxf(fmaxf(fmaxf(o[0], o[1]), fmaxf(o[2], o[3])), o[4]);
                    float s = 0.f;
                    #pragma unroll
                    for (int c = 0; c < 5; ++c) { o[c] = __expf(o[c] - mx); s += o[c]; }
                    float inv = 1.f / s;
                    #pragma unroll
                    for (int c = 0; c < 5; ++c) gout[(size_t)r * 5 + c] = o[c] * inv;
                }
            }
        }
    }
}

// ---------------- launch ----------------
extern "C" void kernel_launch(void* const* d_in, const int* in_sizes, int n_in,
                              void* d_out, int out_size) {
    const float* x  = (const float*)d_in[0];
    const float* Wx = (const float*)d_in[1];
    const float* Wh = (const float*)d_in[2];
    const float* br = (const float*)d_in[3];
    const float* W1 = (const float*)d_in[4];
    const float* b1 = (const float*)d_in[5];
    const float* W2 = (const float*)d_in[6];
    const float* b2 = (const float*)d_in[7];

    cudaFuncSetAttribute(rnn_kernel, cudaFuncAttributeMaxDynamicSharedMemorySize, SMEM_TOTAL);
    const int grid = (Bn + BM - 1) / BM;   // 147 CTAs -> single wave on 148 SMs
    rnn_kernel<<<grid, NT, SMEM_TOTAL>>>(x, Wx, Wh, br, W1, b1, W2, b2, (float*)d_out);
}